// round 4
// baseline (speedup 1.0000x reference)
#include <cuda_runtime.h>
#include <cstdint>

// Problem constants (match reference_code)
#define N_USER   100000
#define N_ITEM   50000
#define NTOT     150000      // N_USER + N_ITEM
#define D        64
#define NNZ_CNT  4000000
#define BATCH    2048
#define NEGS     8192        // 4 * BATCH
#define NOUT     (BATCH + BATCH + NEGS)   // 12288 output rows

// Scratch: device globals (zero-initialized at module load).
// g_acc rows are re-zeroed each launch for exactly the rows we touch,
// so graph replays see a consistent starting state.
__device__ float g_acc[(size_t)NTOT * D];   // ~38.4 MB
__device__ int   g_flag[NTOT];              // 600 KB

// ---------------------------------------------------------------------------
// Kernel 1: clear row flags
// ---------------------------------------------------------------------------
__global__ void k_clear_flags()
{
    int i = blockIdx.x * blockDim.x + threadIdx.x;
    if (i < NTOT) g_flag[i] = 0;
}

// ---------------------------------------------------------------------------
// Kernel 2: mark target rows + zero their accumulator rows
// Layout: 16 threads per output row (float4 each covers D=64 floats)
// Duplicate rows just write the same zeros / flag value — benign races.
// ---------------------------------------------------------------------------
__global__ void k_mark(const int* __restrict__ users,
                       const int* __restrict__ pos,
                       const int* __restrict__ neg)
{
    int tid = blockIdx.x * blockDim.x + threadIdx.x;
    int rowIdx = tid >> 4;          // / 16
    int l16    = tid & 15;
    if (rowIdx >= NOUT) return;

    int row;
    if (rowIdx < BATCH)            row = users[rowIdx];
    else if (rowIdx < 2 * BATCH)   row = N_USER + pos[rowIdx - BATCH];
    else                           row = N_USER + neg[rowIdx - 2 * BATCH];

    if (l16 == 0) g_flag[row] = 1;
    float4 z = make_float4(0.f, 0.f, 0.f, 0.f);
    reinterpret_cast<float4*>(g_acc + (size_t)row * D)[l16] = z;
}

// ---------------------------------------------------------------------------
// Kernel 3: filtered SpMM.
// Each warp owns 32 consecutive nnz: lane checks flag of its row; ballot;
// for each hit the full warp gathers e0[col] (64 floats, float2/lane),
// scales by val, and vector-reduces into g_acc[row].
// ---------------------------------------------------------------------------
__global__ void k_spmm(const int*   __restrict__ rows,
                       const int*   __restrict__ cols,
                       const float* __restrict__ vals,
                       const float* __restrict__ ue,
                       const float* __restrict__ ie)
{
    const int lane   = threadIdx.x & 31;
    const long warp  = (long)blockIdx.x * (blockDim.x >> 5) + (threadIdx.x >> 5);
    const long idx   = warp * 32 + lane;

    int   r = 0, c = 0;
    float v = 0.f;
    bool  hit = false;
    if (idx < NNZ_CNT) {
        r = rows[idx];
        hit = (g_flag[r] != 0);
        if (hit) {
            c = cols[idx];
            v = vals[idx];
        }
    }

    unsigned m = __ballot_sync(0xffffffffu, hit);
    while (m) {
        int b = __ffs(m) - 1;
        m &= m - 1;
        int   rr = __shfl_sync(0xffffffffu, r, b);
        int   cc = __shfl_sync(0xffffffffu, c, b);
        float vv = __shfl_sync(0xffffffffu, v, b);

        const float* src = (cc < N_USER)
                         ? (ue + (size_t)cc * D)
                         : (ie + (size_t)(cc - N_USER) * D);
        float2 e = reinterpret_cast<const float2*>(src)[lane];

        float* dst = g_acc + (size_t)rr * D + lane * 2;
        asm volatile("red.global.add.v2.f32 [%0], {%1, %2};"
                     :: "l"(dst), "f"(e.x * vv), "f"(e.y * vv) : "memory");
    }
}

// ---------------------------------------------------------------------------
// Kernel 4: gather + combine: out[j] = (e0[row] + 3*acc[row]) / 4
// 32 threads (float2 each) per output row.
// ---------------------------------------------------------------------------
__global__ void k_out(const int* __restrict__ users,
                      const int* __restrict__ pos,
                      const int* __restrict__ neg,
                      const float* __restrict__ ue,
                      const float* __restrict__ ie,
                      float* __restrict__ out)
{
    int tid = blockIdx.x * blockDim.x + threadIdx.x;
    int rowIdx = tid >> 5;
    int l      = tid & 31;
    if (rowIdx >= NOUT) return;

    int row;
    if (rowIdx < BATCH)            row = users[rowIdx];
    else if (rowIdx < 2 * BATCH)   row = N_USER + pos[rowIdx - BATCH];
    else                           row = N_USER + neg[rowIdx - 2 * BATCH];

    const float* src = (row < N_USER)
                     ? (ue + (size_t)row * D)
                     : (ie + (size_t)(row - N_USER) * D);
    float2 e = reinterpret_cast<const float2*>(src)[l];
    float2 a = reinterpret_cast<const float2*>(g_acc + (size_t)row * D)[l];

    float2 o;
    o.x = (e.x + 3.0f * a.x) * 0.25f;
    o.y = (e.y + 3.0f * a.y) * 0.25f;
    reinterpret_cast<float2*>(out)[(size_t)rowIdx * (D / 2) + l] = o;
}

// ---------------------------------------------------------------------------
// Launch
// Inputs (metadata order): 0 users[2048] i32, 1 pos_items[2048] i32,
// 2 neg_items[8192] i32, 3 mask[1] f32, 4 norm_adj[1] f32,
// 5 user_emb[100000*64] f32, 6 item_emb[50000*64] f32,
// 7 adj_row[4M] i32, 8 adj_col[4M] i32, 9 adj_val[4M] f32.
// Output: float32, 12288*64 = 786432 elements.
// ---------------------------------------------------------------------------
extern "C" void kernel_launch(void* const* d_in, const int* in_sizes, int n_in,
                              void* d_out, int out_size)
{
    const int*   users = (const int*)  d_in[0];
    const int*   pos   = (const int*)  d_in[1];
    const int*   neg   = (const int*)  d_in[2];
    const float* ue    = (const float*)d_in[5];
    const float* ie    = (const float*)d_in[6];
    const int*   arow  = (const int*)  d_in[7];
    const int*   acol  = (const int*)  d_in[8];
    const float* aval  = (const float*)d_in[9];
    float*       out   = (float*)d_out;

    // 1. clear flags
    k_clear_flags<<<(NTOT + 255) / 256, 256>>>();

    // 2. mark target rows + zero their acc rows (NOUT * 16 threads)
    k_mark<<<(NOUT * 16 + 255) / 256, 256>>>(users, pos, neg);

    // 3. filtered SpMM: one warp per 32 nnz
    {
        const int threads = 256;                       // 8 warps/block
        const long warps  = (NNZ_CNT + 31) / 32;       // 125000
        const int blocks  = (int)((warps + 7) / 8);    // 15625
        k_spmm<<<blocks, threads>>>(arow, acol, aval, ue, ie);
    }

    // 4. gather + combine (NOUT * 32 threads)
    k_out<<<(NOUT * 32 + 255) / 256, 256>>>(users, pos, neg, ue, ie, out);
}

// round 5
// speedup vs baseline: 1.4662x; 1.4662x over previous
#include <cuda_runtime.h>
#include <cstdint>

// Problem constants (match reference_code)
#define N_USER   100000
#define N_ITEM   50000
#define NTOT     150000      // N_USER + N_ITEM
#define D        64
#define NNZ_CNT  4000000
#define BATCH    2048
#define NEGS     8192        // 4 * BATCH
#define NOUT     (BATCH + BATCH + NEGS)   // 12288 output rows
#define BM_WORDS ((NTOT + 31) / 32)       // 4688

#define FULLMASK 0xffffffffu

// Scratch (device globals; rows we touch are re-initialized every launch,
// so graph replays are self-consistent).
__device__ float    g_acc[(size_t)NTOT * D];   // ~38.4 MB
__device__ unsigned g_bm[BM_WORDS];            // ~19 KB row bitmap

// ---------------------------------------------------------------------------
// Kernel 1: clear the row bitmap (19 KB)
// ---------------------------------------------------------------------------
__global__ void k_clear_bm()
{
    int i = blockIdx.x * blockDim.x + threadIdx.x;
    if (i < BM_WORDS) g_bm[i] = 0u;
}

// ---------------------------------------------------------------------------
// Kernel 2: mark target rows in bitmap + seed g_acc[row] = e0[row] / 3
// 16 threads per output row, float4 each. Duplicate rows: same value, benign.
// ---------------------------------------------------------------------------
__global__ void k_mark(const int* __restrict__ users,
                       const int* __restrict__ pos,
                       const int* __restrict__ neg,
                       const float* __restrict__ ue,
                       const float* __restrict__ ie)
{
    int tid = blockIdx.x * blockDim.x + threadIdx.x;
    int rowIdx = tid >> 4;
    int l16    = tid & 15;
    if (rowIdx >= NOUT) return;

    int row;
    if (rowIdx < BATCH)            row = users[rowIdx];
    else if (rowIdx < 2 * BATCH)   row = N_USER + pos[rowIdx - BATCH];
    else                           row = N_USER + neg[rowIdx - 2 * BATCH];

    if (l16 == 0) atomicOr(&g_bm[row >> 5], 1u << (row & 31));

    const float* src = (row < N_USER)
                     ? (ue + (size_t)row * D)
                     : (ie + (size_t)(row - N_USER) * D);
    float4 e = reinterpret_cast<const float4*>(src)[l16];
    const float k = 1.0f / 3.0f;
    e.x *= k; e.y *= k; e.z *= k; e.w *= k;
    reinterpret_cast<float4*>(g_acc + (size_t)row * D)[l16] = e;
}

// ---------------------------------------------------------------------------
// Kernel 3: filtered SpMM.
// Each warp owns 128 consecutive nnz (int4 per lane). Per sub-slot j:
// ballot hit lanes; service TWO hits per iteration (half-warp each) with
// float4 gathers and red.global.add.v4.f32.
// ---------------------------------------------------------------------------
__global__ void k_spmm(const int*   __restrict__ rows,
                       const int*   __restrict__ cols,
                       const float* __restrict__ vals,
                       const float* __restrict__ ue,
                       const float* __restrict__ ie)
{
    const int  lane = threadIdx.x & 31;
    const long warp = (long)blockIdx.x * (blockDim.x >> 5) + (threadIdx.x >> 5);
    const long base = warp * 128;
    if (base >= NNZ_CNT) return;           // NNZ % 128 == 0: chunks are all-in or all-out

    const long myBase = base + (long)lane * 4;
    const int4 r4 = *reinterpret_cast<const int4*>(rows + myBase);
    int r[4] = { r4.x, r4.y, r4.z, r4.w };

    const int l16 = lane & 15;

#pragma unroll
    for (int j = 0; j < 4; j++) {
        int  rj  = r[j];
        bool hit = (g_bm[rj >> 5] >> (rj & 31)) & 1u;

        int   cj = 0;
        float vj = 0.f;
        if (hit) {
            cj = cols[myBase + j];
            vj = vals[myBase + j];
        }

        unsigned m = __ballot_sync(FULLMASK, hit);
        while (m) {
            int b0 = __ffs(m) - 1;  m &= m - 1;
            int b1 = -1;
            if (m) { b1 = __ffs(m) - 1;  m &= m - 1; }

            int  b   = (lane < 16) ? b0 : b1;
            bool act = (b >= 0);
            int  bb  = act ? b : 0;

            int   rr = __shfl_sync(FULLMASK, rj, bb);
            int   cc = __shfl_sync(FULLMASK, cj, bb);
            float vv = __shfl_sync(FULLMASK, vj, bb);

            if (act) {
                const float* src = (cc < N_USER)
                                 ? (ue + (size_t)cc * D)
                                 : (ie + (size_t)(cc - N_USER) * D);
                float4 e = reinterpret_cast<const float4*>(src)[l16];
                float* dst = g_acc + (size_t)rr * D + l16 * 4;
                asm volatile("red.global.add.v4.f32 [%0], {%1, %2, %3, %4};"
                             :: "l"(dst),
                                "f"(e.x * vv), "f"(e.y * vv),
                                "f"(e.z * vv), "f"(e.w * vv)
                             : "memory");
            }
        }
    }
}

// ---------------------------------------------------------------------------
// Kernel 4: out[j] = 0.75 * g_acc[row]   (since acc = e0/3 + ae0)
// 16 threads per output row, float4 each.
// ---------------------------------------------------------------------------
__global__ void k_out(const int* __restrict__ users,
                      const int* __restrict__ pos,
                      const int* __restrict__ neg,
                      float* __restrict__ out)
{
    int tid = blockIdx.x * blockDim.x + threadIdx.x;
    int rowIdx = tid >> 4;
    int l16    = tid & 15;
    if (rowIdx >= NOUT) return;

    int row;
    if (rowIdx < BATCH)            row = users[rowIdx];
    else if (rowIdx < 2 * BATCH)   row = N_USER + pos[rowIdx - BATCH];
    else                           row = N_USER + neg[rowIdx - 2 * BATCH];

    float4 a = reinterpret_cast<const float4*>(g_acc + (size_t)row * D)[l16];
    a.x *= 0.75f; a.y *= 0.75f; a.z *= 0.75f; a.w *= 0.75f;
    reinterpret_cast<float4*>(out)[(size_t)rowIdx * (D / 4) + l16] = a;
}

// ---------------------------------------------------------------------------
// Launch
// Inputs: 0 users[2048] i32, 1 pos_items[2048] i32, 2 neg_items[8192] i32,
// 3 mask f32, 4 norm_adj f32, 5 user_emb f32, 6 item_emb f32,
// 7 adj_row i32, 8 adj_col i32, 9 adj_val f32. Output: f32, 12288*64.
// ---------------------------------------------------------------------------
extern "C" void kernel_launch(void* const* d_in, const int* in_sizes, int n_in,
                              void* d_out, int out_size)
{
    const int*   users = (const int*)  d_in[0];
    const int*   pos   = (const int*)  d_in[1];
    const int*   neg   = (const int*)  d_in[2];
    const float* ue    = (const float*)d_in[5];
    const float* ie    = (const float*)d_in[6];
    const int*   arow  = (const int*)  d_in[7];
    const int*   acol  = (const int*)  d_in[8];
    const float* aval  = (const float*)d_in[9];
    float*       out   = (float*)d_out;

    // 1. clear bitmap
    k_clear_bm<<<(BM_WORDS + 255) / 256, 256>>>();

    // 2. mark rows + seed acc = e0/3   (NOUT * 16 threads)
    k_mark<<<(NOUT * 16 + 255) / 256, 256>>>(users, pos, neg, ue, ie);

    // 3. filtered SpMM: one warp per 128 nnz
    {
        const int  threads = 256;                      // 8 warps/block
        const long warps   = (NNZ_CNT + 127) / 128;    // 31250
        const int  blocks  = (int)((warps + 7) / 8);   // 3907
        k_spmm<<<blocks, threads>>>(arow, acol, aval, ue, ie);
    }

    // 4. gather + scale   (NOUT * 16 threads)
    k_out<<<(NOUT * 16 + 255) / 256, 256>>>(users, pos, neg, out);
}